// round 1
// baseline (speedup 1.0000x reference)
#include <cuda_runtime.h>

#define N   192
#define N2  (N*N)
#define N3  (N*N*N)

// ---- constants (match reference exactly) ----
#define DT      0.01f
#define HCELL   0.1f
#define GDT     (9.81f * 0.01f)                 // gravity * dt
#define SCALE   (DT / HCELL)                    // 0.1
#define ALPHA   (0.01f * 0.01f / (0.1f * 0.1f)) // visc*dt/h^2 = 0.01
#define INVDIF  (1.0f / (1.0f + 6.0f * ALPHA))
#define INV2H   (1.0f / (2.0f * HCELL))         // 5.0
#define SIXTH   (1.0f / 6.0f)

// ---- scratch (allocation-free rule: __device__ globals) ----
__device__ float g_velA[3 * N3];
__device__ float g_velB[3 * N3];
__device__ float g_div [N3];
__device__ float g_pA  [N3];
__device__ float g_pB  [N3];

// ============================================================
// 1) gravity + semi-Lagrangian advection (fused)
// ============================================================
__global__ void k_advect(const float* __restrict__ vin, float* __restrict__ vout) {
    int idx = blockIdx.x * blockDim.x + threadIdx.x;
    if (idx >= N3) return;
    int k = idx % N;
    int j = (idx / N) % N;
    int i = idx / N2;

    float vx = vin[idx];
    float vy = vin[N3 + idx];
    float vz = vin[2 * N3 + idx] - GDT;   // gravity applied before advection

    float px = fminf(fmaxf((float)i - vx * SCALE, 0.0f), (float)(N - 2));
    float py = fminf(fmaxf((float)j - vy * SCALE, 0.0f), (float)(N - 2));
    float pz = fminf(fmaxf((float)k - vz * SCALE, 0.0f), (float)(N - 2));

    int ix = (int)px, iy = (int)py, iz = (int)pz;   // floor (non-negative)
    float wx1 = px - (float)ix, wy1 = py - (float)iy, wz1 = pz - (float)iz;
    float wx0 = 1.0f - wx1,     wy0 = 1.0f - wy1,    wz0 = 1.0f - wz1;

    float w000 = wx0 * wy0 * wz0, w001 = wx0 * wy0 * wz1;
    float w010 = wx0 * wy1 * wz0, w011 = wx0 * wy1 * wz1;
    float w100 = wx1 * wy0 * wz0, w101 = wx1 * wy0 * wz1;
    float w110 = wx1 * wy1 * wz0, w111 = wx1 * wy1 * wz1;

    int b = (ix * N + iy) * N + iz;

    #pragma unroll
    for (int c = 0; c < 3; c++) {
        const float* f = vin + c * N3;
        float v = f[b]          * w000 + f[b + 1]          * w001
                + f[b + N]      * w010 + f[b + N + 1]      * w011
                + f[b + N2]     * w100 + f[b + N2 + 1]     * w101
                + f[b + N2 + N] * w110 + f[b + N2 + N + 1] * w111;
        if (c == 2) v -= GDT;   // gather source also has gravity applied; weights sum to 1
        vout[c * N3 + idx] = v;
    }
}

// ============================================================
// 2) one Jacobi diffusion sweep (all 3 components), ping-pong
// ============================================================
__global__ void k_diffuse(const float* __restrict__ vin, float* __restrict__ vout) {
    int t = blockIdx.x * blockDim.x + threadIdx.x;
    if (t >= 3 * N3) return;
    int cell = t % N3;
    int k = cell % N;
    int j = (cell / N) % N;
    int i = cell / N2;

    float c0 = vin[t];
    float out;
    if (i == 0 || i == N - 1 || j == 0 || j == N - 1 || k == 0 || k == N - 1) {
        out = c0;   // boundary passes through
    } else {
        float nb = vin[t + N2] + vin[t - N2]
                 + vin[t + N]  + vin[t - N]
                 + vin[t + 1]  + vin[t - 1];
        out = (c0 + ALPHA * nb) * INVDIF;
    }
    vout[t] = out;
}

// ============================================================
// 3) divergence (interior; zero boundary)
// ============================================================
__global__ void k_divergence(const float* __restrict__ v, float* __restrict__ dv) {
    int idx = blockIdx.x * blockDim.x + threadIdx.x;
    if (idx >= N3) return;
    int k = idx % N;
    int j = (idx / N) % N;
    int i = idx / N2;

    float out = 0.0f;
    if (!(i == 0 || i == N - 1 || j == 0 || j == N - 1 || k == 0 || k == N - 1)) {
        out = ((v[idx + N2]          - v[idx - N2])
             + (v[N3 + idx + N]      - v[N3 + idx - N])
             + (v[2 * N3 + idx + 1]  - v[2 * N3 + idx - 1])) * INV2H;
    }
    dv[idx] = out;
}

// ============================================================
// 4a) first pressure sweep (p_prev == 0  =>  p = div/6 interior)
// ============================================================
__global__ void k_pressure0(const float* __restrict__ dv, float* __restrict__ p) {
    int idx = blockIdx.x * blockDim.x + threadIdx.x;
    if (idx >= N3) return;
    int k = idx % N;
    int j = (idx / N) % N;
    int i = idx / N2;

    float out = 0.0f;
    if (!(i == 0 || i == N - 1 || j == 0 || j == N - 1 || k == 0 || k == N - 1))
        out = dv[idx] * SIXTH;
    p[idx] = out;
}

// ============================================================
// 4b) generic pressure Jacobi sweep
// ============================================================
__global__ void k_pressure(const float* __restrict__ dv,
                           const float* __restrict__ pin,
                           float* __restrict__ pout) {
    int idx = blockIdx.x * blockDim.x + threadIdx.x;
    if (idx >= N3) return;
    int k = idx % N;
    int j = (idx / N) % N;
    int i = idx / N2;

    float out = 0.0f;
    if (!(i == 0 || i == N - 1 || j == 0 || j == N - 1 || k == 0 || k == N - 1)) {
        float nb = pin[idx + N2] + pin[idx - N2]
                 + pin[idx + N]  + pin[idx - N]
                 + pin[idx + 1]  + pin[idx - 1];
        out = (dv[idx] + nb) * SIXTH;
    }
    pout[idx] = out;
}

// ============================================================
// 5) subtract pressure gradient -> final output
// ============================================================
__global__ void k_project(const float* __restrict__ v,
                          const float* __restrict__ p,
                          float* __restrict__ out) {
    int idx = blockIdx.x * blockDim.x + threadIdx.x;
    if (idx >= N3) return;
    int k = idx % N;
    int j = (idx / N) % N;
    int i = idx / N2;

    float v0 = v[idx], v1 = v[N3 + idx], v2 = v[2 * N3 + idx];
    if (!(i == 0 || i == N - 1 || j == 0 || j == N - 1 || k == 0 || k == N - 1)) {
        v0 -= (p[idx + N2] - p[idx - N2]) * INV2H;
        v1 -= (p[idx + N]  - p[idx - N])  * INV2H;
        v2 -= (p[idx + 1]  - p[idx - 1])  * INV2H;
    }
    out[idx]          = v0;
    out[N3 + idx]     = v1;
    out[2 * N3 + idx] = v2;
}

// ============================================================
// host launcher (graph-capturable: kernel launches only)
// ============================================================
extern "C" void kernel_launch(void* const* d_in, const int* in_sizes, int n_in,
                              void* d_out, int out_size) {
    const float* vin = (const float*)d_in[0];
    float* out = (float*)d_out;

    float *velA, *velB, *dv, *pA, *pB;
    cudaGetSymbolAddress((void**)&velA, g_velA);
    cudaGetSymbolAddress((void**)&velB, g_velB);
    cudaGetSymbolAddress((void**)&dv,   g_div);
    cudaGetSymbolAddress((void**)&pA,   g_pA);
    cudaGetSymbolAddress((void**)&pB,   g_pB);

    const int T = 256;
    const int blocksCell = (N3 + T - 1) / T;
    const int blocksVec  = (3 * N3 + T - 1) / T;

    // gravity + advect
    k_advect<<<blocksCell, T>>>(vin, velA);

    // 5 Jacobi diffusion sweeps (ping-pong)
    float* a = velA; float* b = velB;
    for (int s = 0; s < 5; s++) {
        k_diffuse<<<blocksVec, T>>>(a, b);
        float* tmp = a; a = b; b = tmp;
    }
    // result now in `a`

    // divergence
    k_divergence<<<blocksCell, T>>>(a, dv);

    // 20 pressure Jacobi sweeps (first specialized for p=0)
    k_pressure0<<<blocksCell, T>>>(dv, pA);
    float* pa = pA; float* pb = pB;
    for (int s = 0; s < 19; s++) {
        k_pressure<<<blocksCell, T>>>(dv, pa, pb);
        float* tmp = pa; pa = pb; pb = tmp;
    }
    // result now in `pa`

    // gradient subtract -> output
    k_project<<<blocksCell, T>>>(a, pa, out);
}

// round 2
// speedup vs baseline: 1.7212x; 1.7212x over previous
#include <cuda_runtime.h>

#define N    192
#define N4   (N/4)          // 48 float4 per k-row
#define N2   (N*N)
#define N3   (N*N*N)
#define C4   (N3/4)         // float4 cells per scalar field
#define SI4  (N2/4)         // i-stride in float4 units = 9216
#define SJ4  (N/4)          // j-stride in float4 units = 48

#define DT      0.01f
#define HCELL   0.1f
#define GDT     (9.81f * 0.01f)
#define SCALE   (DT / HCELL)
#define ALPHA   (0.01f * 0.01f / (0.1f * 0.1f))
#define INVDIF  (1.0f / (1.0f + 6.0f * ALPHA))
#define INV2H   (1.0f / (2.0f * HCELL))
#define SIXTH   (1.0f / 6.0f)

__device__ float g_velA[3 * N3];
__device__ float g_velB[3 * N3];
__device__ float g_div [N3];
__device__ float g_pA  [N3];
__device__ float g_pB  [N3];

// ============================================================
// 1) gravity + semi-Lagrangian advection (fused)
// ============================================================
__global__ void k_advect(const float* __restrict__ vin, float* __restrict__ vout) {
    int idx = blockIdx.x * blockDim.x + threadIdx.x;
    if (idx >= N3) return;
    int k = idx % N;
    int j = (idx / N) % N;
    int i = idx / N2;

    float vx = vin[idx];
    float vy = vin[N3 + idx];
    float vz = vin[2 * N3 + idx] - GDT;

    float px = fminf(fmaxf((float)i - vx * SCALE, 0.0f), (float)(N - 2));
    float py = fminf(fmaxf((float)j - vy * SCALE, 0.0f), (float)(N - 2));
    float pz = fminf(fmaxf((float)k - vz * SCALE, 0.0f), (float)(N - 2));

    int ix = (int)px, iy = (int)py, iz = (int)pz;
    float wx1 = px - (float)ix, wy1 = py - (float)iy, wz1 = pz - (float)iz;
    float wx0 = 1.0f - wx1,     wy0 = 1.0f - wy1,    wz0 = 1.0f - wz1;

    float w000 = wx0 * wy0 * wz0, w001 = wx0 * wy0 * wz1;
    float w010 = wx0 * wy1 * wz0, w011 = wx0 * wy1 * wz1;
    float w100 = wx1 * wy0 * wz0, w101 = wx1 * wy0 * wz1;
    float w110 = wx1 * wy1 * wz0, w111 = wx1 * wy1 * wz1;

    int b = (ix * N + iy) * N + iz;

    #pragma unroll
    for (int c = 0; c < 3; c++) {
        const float* f = vin + c * N3;
        float v = f[b]          * w000 + f[b + 1]          * w001
                + f[b + N]      * w010 + f[b + N + 1]      * w011
                + f[b + N2]     * w100 + f[b + N2 + 1]     * w101
                + f[b + N2 + N] * w110 + f[b + N2 + N + 1] * w111;
        if (c == 2) v -= GDT;
        vout[c * N3 + idx] = v;
    }
}

// ============================================================
// 2) one Jacobi diffusion sweep, float4-vectorized (3 comps)
// ============================================================
__global__ void k_diffuse4(const float4* __restrict__ vin, float4* __restrict__ vout) {
    int t = blockIdx.x * blockDim.x + threadIdx.x;
    if (t >= 3 * C4) return;
    int cell = t % C4;
    int k4 = cell % N4;
    int j  = (cell / N4) % N;
    int i  = cell / SI4;

    float4 c = vin[t];
    if (i == 0 || i == N - 1 || j == 0 || j == N - 1) { vout[t] = c; return; }

    float4 a1 = vin[t + SI4], a2 = vin[t - SI4];   // i +/- 1
    float4 b1 = vin[t + SJ4], b2 = vin[t - SJ4];   // j +/- 1
    const float* s = (const float*)vin;
    float lm = (k4 > 0)      ? s[4 * t - 1] : 0.0f;
    float rp = (k4 < N4 - 1) ? s[4 * t + 4] : 0.0f;

    float4 o;
    o.x = (k4 == 0)
        ? c.x
        : (c.x + ALPHA * (a1.x + a2.x + b1.x + b2.x + lm  + c.y)) * INVDIF;
    o.y =   (c.y + ALPHA * (a1.y + a2.y + b1.y + b2.y + c.x + c.z)) * INVDIF;
    o.z =   (c.z + ALPHA * (a1.z + a2.z + b1.z + b2.z + c.y + c.w)) * INVDIF;
    o.w = (k4 == N4 - 1)
        ? c.w
        : (c.w + ALPHA * (a1.w + a2.w + b1.w + b2.w + c.z + rp )) * INVDIF;
    vout[t] = o;
}

// ============================================================
// 3) divergence + first pressure sweep fused (p1 = div/6)
// ============================================================
__global__ void k_div_p0(const float4* __restrict__ v,
                         float4* __restrict__ dv, float4* __restrict__ p) {
    int t = blockIdx.x * blockDim.x + threadIdx.x;
    if (t >= C4) return;
    int k4 = t % N4;
    int j  = (t / N4) % N;
    int i  = t / SI4;

    float4 d = make_float4(0.f, 0.f, 0.f, 0.f);
    if (!(i == 0 || i == N - 1 || j == 0 || j == N - 1)) {
        const float4* vx = v;
        const float4* vy = v + C4;
        const float4* vz = v + 2 * C4;
        float4 xa = vx[t + SI4], xb = vx[t - SI4];
        float4 ya = vy[t + SJ4], yb = vy[t - SJ4];
        float4 zc = vz[t];
        const float* zs = (const float*)vz;
        float zl = (k4 > 0)      ? zs[4 * t - 1] : 0.0f;
        float zr = (k4 < N4 - 1) ? zs[4 * t + 4] : 0.0f;

        if (k4 != 0)
            d.x = ((xa.x - xb.x) + (ya.x - yb.x) + (zc.y - zl))   * INV2H;
        d.y =     ((xa.y - xb.y) + (ya.y - yb.y) + (zc.z - zc.x)) * INV2H;
        d.z =     ((xa.z - xb.z) + (ya.z - yb.z) + (zc.w - zc.y)) * INV2H;
        if (k4 != N4 - 1)
            d.w = ((xa.w - xb.w) + (ya.w - yb.w) + (zr   - zc.z)) * INV2H;
    }
    dv[t] = d;
    p[t] = make_float4(d.x * SIXTH, d.y * SIXTH, d.z * SIXTH, d.w * SIXTH);
}

// ============================================================
// 4) generic pressure Jacobi sweep, float4-vectorized
// ============================================================
__global__ void k_pressure4(const float4* __restrict__ dv,
                            const float4* __restrict__ pin,
                            float4* __restrict__ pout) {
    int t = blockIdx.x * blockDim.x + threadIdx.x;
    if (t >= C4) return;
    int k4 = t % N4;
    int j  = (t / N4) % N;
    int i  = t / SI4;

    if (i == 0 || i == N - 1 || j == 0 || j == N - 1) {
        pout[t] = make_float4(0.f, 0.f, 0.f, 0.f);
        return;
    }
    float4 c  = pin[t];
    float4 a1 = pin[t + SI4], a2 = pin[t - SI4];
    float4 b1 = pin[t + SJ4], b2 = pin[t - SJ4];
    float4 d  = dv[t];
    const float* s = (const float*)pin;
    float lm = (k4 > 0)      ? s[4 * t - 1] : 0.0f;
    float rp = (k4 < N4 - 1) ? s[4 * t + 4] : 0.0f;

    float4 o;
    o.x = (k4 == 0)      ? 0.0f
        : (d.x + a1.x + a2.x + b1.x + b2.x + lm  + c.y) * SIXTH;
    o.y =  (d.y + a1.y + a2.y + b1.y + b2.y + c.x + c.z) * SIXTH;
    o.z =  (d.z + a1.z + a2.z + b1.z + b2.z + c.y + c.w) * SIXTH;
    o.w = (k4 == N4 - 1) ? 0.0f
        : (d.w + a1.w + a2.w + b1.w + b2.w + c.z + rp ) * SIXTH;
    pout[t] = o;
}

// ============================================================
// 5) subtract pressure gradient -> output, float4-vectorized
// ============================================================
__global__ void k_project4(const float4* __restrict__ v,
                           const float4* __restrict__ p,
                           float4* __restrict__ out) {
    int t = blockIdx.x * blockDim.x + threadIdx.x;
    if (t >= C4) return;
    int k4 = t % N4;
    int j  = (t / N4) % N;
    int i  = t / SI4;

    float4 v0 = v[t], v1 = v[t + C4], v2 = v[t + 2 * C4];

    if (!(i == 0 || i == N - 1 || j == 0 || j == N - 1)) {
        float4 pa = p[t + SI4], pb = p[t - SI4];
        float4 pc = p[t + SJ4], pd = p[t - SJ4];
        float4 pz = p[t];
        const float* s = (const float*)p;
        float pl = (k4 > 0)      ? s[4 * t - 1] : 0.0f;
        float pr = (k4 < N4 - 1) ? s[4 * t + 4] : 0.0f;

        if (k4 != 0) {
            v0.x -= (pa.x - pb.x) * INV2H;
            v1.x -= (pc.x - pd.x) * INV2H;
            v2.x -= (pz.y - pl)   * INV2H;
        }
        v0.y -= (pa.y - pb.y) * INV2H;
        v1.y -= (pc.y - pd.y) * INV2H;
        v2.y -= (pz.z - pz.x) * INV2H;

        v0.z -= (pa.z - pb.z) * INV2H;
        v1.z -= (pc.z - pd.z) * INV2H;
        v2.z -= (pz.w - pz.y) * INV2H;

        if (k4 != N4 - 1) {
            v0.w -= (pa.w - pb.w) * INV2H;
            v1.w -= (pc.w - pd.w) * INV2H;
            v2.w -= (pr   - pz.z) * INV2H;
        }
    }
    out[t]          = v0;
    out[t + C4]     = v1;
    out[t + 2 * C4] = v2;
}

// ============================================================
// host launcher (graph-capturable: kernel launches only)
// ============================================================
extern "C" void kernel_launch(void* const* d_in, const int* in_sizes, int n_in,
                              void* d_out, int out_size) {
    const float* vin = (const float*)d_in[0];
    float* out = (float*)d_out;

    float *velA, *velB, *dv, *pA, *pB;
    cudaGetSymbolAddress((void**)&velA, g_velA);
    cudaGetSymbolAddress((void**)&velB, g_velB);
    cudaGetSymbolAddress((void**)&dv,   g_div);
    cudaGetSymbolAddress((void**)&pA,   g_pA);
    cudaGetSymbolAddress((void**)&pB,   g_pB);

    const int T = 256;
    const int blocksCell  = (N3 + T - 1) / T;          // scalar advect
    const int blocksC4    = (C4 + T - 1) / T;          // float4 scalar-field
    const int blocksV4    = (3 * C4 + T - 1) / T;      // float4 vector-field

    // gravity + advect
    k_advect<<<blocksCell, T>>>(vin, velA);

    // 5 Jacobi diffusion sweeps (ping-pong, vectorized)
    float* a = velA; float* b = velB;
    for (int s = 0; s < 5; s++) {
        k_diffuse4<<<blocksV4, T>>>((const float4*)a, (float4*)b);
        float* tmp = a; a = b; b = tmp;
    }

    // divergence + first pressure sweep fused
    k_div_p0<<<blocksC4, T>>>((const float4*)a, (float4*)dv, (float4*)pA);

    // 19 remaining pressure Jacobi sweeps (ping-pong, vectorized)
    float* pa = pA; float* pb = pB;
    for (int s = 0; s < 19; s++) {
        k_pressure4<<<blocksC4, T>>>((const float4*)dv, (const float4*)pa, (float4*)pb);
        float* tmp = pa; pa = pb; pb = tmp;
    }

    // gradient subtract -> output
    k_project4<<<blocksC4, T>>>((const float4*)a, (const float4*)pa, (float4*)out);
}

// round 3
// speedup vs baseline: 1.7868x; 1.0381x over previous
#include <cuda_runtime.h>

#define N    192
#define N4   (N/4)          // 48 float4 per k-row
#define N2   (N*N)
#define N3   (N*N*N)
#define C4   (N3/4)         // float4 cells per scalar field
#define SI4  (N2/4)         // i-stride in float4 units
#define SJ4  (N/4)          // j-stride in float4 units

#define DT      0.01f
#define HCELL   0.1f
#define GDT     (9.81f * 0.01f)
#define SCALE   (DT / HCELL)
#define ALPHA   (0.01f * 0.01f / (0.1f * 0.1f))
#define INVDIF  (1.0f / (1.0f + 6.0f * ALPHA))
#define INV2H   (1.0f / (2.0f * HCELL))
#define SIXTH   (1.0f / 6.0f)

__device__ float g_velA[3 * N3];
__device__ float g_velB[3 * N3];
__device__ float g_div [N3];
__device__ float g_pA  [N3];
__device__ float g_pB  [N3];

// ============================================================
// 1) gravity + semi-Lagrangian advection (fused)
// ============================================================
__global__ void k_advect(const float* __restrict__ vin, float* __restrict__ vout) {
    int idx = blockIdx.x * blockDim.x + threadIdx.x;
    if (idx >= N3) return;
    int k = idx % N;
    int j = (idx / N) % N;
    int i = idx / N2;

    float vx = vin[idx];
    float vy = vin[N3 + idx];
    float vz = vin[2 * N3 + idx] - GDT;

    float px = fminf(fmaxf((float)i - vx * SCALE, 0.0f), (float)(N - 2));
    float py = fminf(fmaxf((float)j - vy * SCALE, 0.0f), (float)(N - 2));
    float pz = fminf(fmaxf((float)k - vz * SCALE, 0.0f), (float)(N - 2));

    int ix = (int)px, iy = (int)py, iz = (int)pz;
    float wx1 = px - (float)ix, wy1 = py - (float)iy, wz1 = pz - (float)iz;
    float wx0 = 1.0f - wx1,     wy0 = 1.0f - wy1,    wz0 = 1.0f - wz1;

    float w000 = wx0 * wy0 * wz0, w001 = wx0 * wy0 * wz1;
    float w010 = wx0 * wy1 * wz0, w011 = wx0 * wy1 * wz1;
    float w100 = wx1 * wy0 * wz0, w101 = wx1 * wy0 * wz1;
    float w110 = wx1 * wy1 * wz0, w111 = wx1 * wy1 * wz1;

    int b = (ix * N + iy) * N + iz;

    #pragma unroll
    for (int c = 0; c < 3; c++) {
        const float* f = vin + c * N3;
        float v = f[b]          * w000 + f[b + 1]          * w001
                + f[b + N]      * w010 + f[b + N + 1]      * w011
                + f[b + N2]     * w100 + f[b + N2 + 1]     * w101
                + f[b + N2 + N] * w110 + f[b + N2 + N + 1] * w111;
        if (c == 2) v -= GDT;
        vout[c * N3 + idx] = v;
    }
}

// ============================================================
// helper: fetch k-neighbors across float4 boundary via shuffle.
// MUST be called by all threads of the warp before any divergence.
// Values are only *used* when k4>0 / k4<N4-1, so row straddles are safe.
// ============================================================
__device__ __forceinline__ void knb(const float4* base, int t, int k4,
                                    float cw, float cx,
                                    float& lm, float& rp) {
    lm = __shfl_up_sync(0xffffffffu, cw, 1);
    rp = __shfl_down_sync(0xffffffffu, cx, 1);
    int lane = threadIdx.x & 31;
    const float* s = (const float*)base;
    if (lane == 0  && k4 > 0)      lm = s[4 * t - 1];
    if (lane == 31 && k4 < N4 - 1) rp = s[4 * t + 4];
}

// ============================================================
// 2) one Jacobi diffusion sweep on ONE component (L2-resident)
// ============================================================
__global__ void k_diffuse1(const float4* __restrict__ vin, float4* __restrict__ vout) {
    int t = blockIdx.x * blockDim.x + threadIdx.x;   // grid sized exactly: no strays
    int k4 = t % N4;
    int j  = (t / N4) % N;
    int i  = t / SI4;

    float4 c = vin[t];
    float lm, rp;
    knb(vin, t, k4, c.w, c.x, lm, rp);

    if (i == 0 || i == N - 1 || j == 0 || j == N - 1) { vout[t] = c; return; }

    float4 a1 = vin[t + SI4], a2 = vin[t - SI4];
    float4 b1 = vin[t + SJ4], b2 = vin[t - SJ4];

    float4 o;
    o.x = (k4 == 0)
        ? c.x
        : (c.x + ALPHA * (a1.x + a2.x + b1.x + b2.x + lm  + c.y)) * INVDIF;
    o.y =   (c.y + ALPHA * (a1.y + a2.y + b1.y + b2.y + c.x + c.z)) * INVDIF;
    o.z =   (c.z + ALPHA * (a1.z + a2.z + b1.z + b2.z + c.y + c.w)) * INVDIF;
    o.w = (k4 == N4 - 1)
        ? c.w
        : (c.w + ALPHA * (a1.w + a2.w + b1.w + b2.w + c.z + rp )) * INVDIF;
    vout[t] = o;
}

// ============================================================
// 3) divergence + first pressure sweep fused (p1 = div/6)
// ============================================================
__global__ void k_div_p0(const float4* __restrict__ v,
                         float4* __restrict__ dv, float4* __restrict__ p) {
    int t = blockIdx.x * blockDim.x + threadIdx.x;
    int k4 = t % N4;
    int j  = (t / N4) % N;
    int i  = t / SI4;

    const float4* vz = v + 2 * C4;
    float4 zc = vz[t];
    float zl, zr;
    knb(vz, t, k4, zc.w, zc.x, zl, zr);

    float4 d = make_float4(0.f, 0.f, 0.f, 0.f);
    if (!(i == 0 || i == N - 1 || j == 0 || j == N - 1)) {
        const float4* vx = v;
        const float4* vy = v + C4;
        float4 xa = vx[t + SI4], xb = vx[t - SI4];
        float4 ya = vy[t + SJ4], yb = vy[t - SJ4];

        if (k4 != 0)
            d.x = ((xa.x - xb.x) + (ya.x - yb.x) + (zc.y - zl))   * INV2H;
        d.y =     ((xa.y - xb.y) + (ya.y - yb.y) + (zc.z - zc.x)) * INV2H;
        d.z =     ((xa.z - xb.z) + (ya.z - yb.z) + (zc.w - zc.y)) * INV2H;
        if (k4 != N4 - 1)
            d.w = ((xa.w - xb.w) + (ya.w - yb.w) + (zr   - zc.z)) * INV2H;
    }
    dv[t] = d;
    p[t] = make_float4(d.x * SIXTH, d.y * SIXTH, d.z * SIXTH, d.w * SIXTH);
}

// ============================================================
// 4) generic pressure Jacobi sweep
// ============================================================
__global__ void k_pressure4(const float4* __restrict__ dv,
                            const float4* __restrict__ pin,
                            float4* __restrict__ pout) {
    int t = blockIdx.x * blockDim.x + threadIdx.x;
    int k4 = t % N4;
    int j  = (t / N4) % N;
    int i  = t / SI4;

    float4 c = pin[t];
    float lm, rp;
    knb(pin, t, k4, c.w, c.x, lm, rp);

    if (i == 0 || i == N - 1 || j == 0 || j == N - 1) {
        pout[t] = make_float4(0.f, 0.f, 0.f, 0.f);
        return;
    }
    float4 a1 = pin[t + SI4], a2 = pin[t - SI4];
    float4 b1 = pin[t + SJ4], b2 = pin[t - SJ4];
    float4 d  = dv[t];

    float4 o;
    o.x = (k4 == 0)      ? 0.0f
        : (d.x + a1.x + a2.x + b1.x + b2.x + lm  + c.y) * SIXTH;
    o.y =  (d.y + a1.y + a2.y + b1.y + b2.y + c.x + c.z) * SIXTH;
    o.z =  (d.z + a1.z + a2.z + b1.z + b2.z + c.y + c.w) * SIXTH;
    o.w = (k4 == N4 - 1) ? 0.0f
        : (d.w + a1.w + a2.w + b1.w + b2.w + c.z + rp ) * SIXTH;
    pout[t] = o;
}

// ============================================================
// 5) subtract pressure gradient -> output
// ============================================================
__global__ void k_project4(const float4* __restrict__ v,
                           const float4* __restrict__ p,
                           float4* __restrict__ out) {
    int t = blockIdx.x * blockDim.x + threadIdx.x;
    int k4 = t % N4;
    int j  = (t / N4) % N;
    int i  = t / SI4;

    float4 pz = p[t];
    float pl, pr;
    knb(p, t, k4, pz.w, pz.x, pl, pr);

    float4 v0 = v[t], v1 = v[t + C4], v2 = v[t + 2 * C4];

    if (!(i == 0 || i == N - 1 || j == 0 || j == N - 1)) {
        float4 pa = p[t + SI4], pb = p[t - SI4];
        float4 pc = p[t + SJ4], pd = p[t - SJ4];

        if (k4 != 0) {
            v0.x -= (pa.x - pb.x) * INV2H;
            v1.x -= (pc.x - pd.x) * INV2H;
            v2.x -= (pz.y - pl)   * INV2H;
        }
        v0.y -= (pa.y - pb.y) * INV2H;
        v1.y -= (pc.y - pd.y) * INV2H;
        v2.y -= (pz.z - pz.x) * INV2H;

        v0.z -= (pa.z - pb.z) * INV2H;
        v1.z -= (pc.z - pd.z) * INV2H;
        v2.z -= (pz.w - pz.y) * INV2H;

        if (k4 != N4 - 1) {
            v0.w -= (pa.w - pb.w) * INV2H;
            v1.w -= (pc.w - pd.w) * INV2H;
            v2.w -= (pr   - pz.z) * INV2H;
        }
    }
    out[t]          = v0;
    out[t + C4]     = v1;
    out[t + 2 * C4] = v2;
}

// ============================================================
// host launcher (graph-capturable: kernel launches only)
// ============================================================
extern "C" void kernel_launch(void* const* d_in, const int* in_sizes, int n_in,
                              void* d_out, int out_size) {
    const float* vin = (const float*)d_in[0];
    float* out = (float*)d_out;

    float *velA, *velB, *dv, *pA, *pB;
    cudaGetSymbolAddress((void**)&velA, g_velA);
    cudaGetSymbolAddress((void**)&velB, g_velB);
    cudaGetSymbolAddress((void**)&dv,   g_div);
    cudaGetSymbolAddress((void**)&pA,   g_pA);
    cudaGetSymbolAddress((void**)&pB,   g_pB);

    const int T = 256;
    const int blocksCell = (N3 + T - 1) / T;   // scalar advect
    const int blocksC4   = C4 / T;             // exact: 6912 blocks, no stray threads

    // gravity + advect
    k_advect<<<blocksCell, T>>>(vin, velA);

    // 5 Jacobi diffusion sweeps, per-component (L2-resident working set)
    for (int c = 0; c < 3; c++) {
        float* a = velA + c * N3;
        float* b = velB + c * N3;
        for (int s = 0; s < 5; s++) {
            k_diffuse1<<<blocksC4, T>>>((const float4*)a, (float4*)b);
            float* tmp = a; a = b; b = tmp;
        }
    }
    // 5 sweeps (odd) -> result in velB for every component
    float* vdif = velB;

    // divergence + first pressure sweep fused
    k_div_p0<<<blocksC4, T>>>((const float4*)vdif, (float4*)dv, (float4*)pA);

    // 19 remaining pressure Jacobi sweeps
    float* pa = pA; float* pb = pB;
    for (int s = 0; s < 19; s++) {
        k_pressure4<<<blocksC4, T>>>((const float4*)dv, (const float4*)pa, (float4*)pb);
        float* tmp = pa; pa = pb; pb = tmp;
    }

    // gradient subtract -> output
    k_project4<<<blocksC4, T>>>((const float4*)vdif, (const float4*)pa, (float4*)out);
}